// round 9
// baseline (speedup 1.0000x reference)
#include <cuda_runtime.h>
#include <cuda_bf16.h>
#include <cstdint>

// ---------------- problem constants ----------------
#define BN 8192
#define DK 128
#define NCLS 2048
constexpr float INV_T = 1.0f / 0.07f;
// exp((v-1)*INV_T) == exp2(v*C1 + C0); +15 exponent shift keeps fp16 normal
constexpr float C1  = 14.2857142857f * 1.4426950408889634f;
constexpr float C0S = -14.2857142857f * 1.4426950408889634f + 15.0f;
constexpr float SCALE = 1.0f / 32768.0f;     // 2^-15, undo the shift

#define NCTA 296          // 148 SMs x 2 CTAs: exactly one wave
#define NTILE 2080        // symmetric tile count

// ---------------- device scratch ----------------
__device__ __nv_bfloat16 g_Ebf[BN * DK];
__device__ float g_S[NCLS * DK];
__device__ int   g_cnt[NCLS];
__device__ float g_Z[BN];
__device__ int   g_lab[BN];
__device__ float g_num;
__device__ int   g_den;
__device__ unsigned g_done;
__device__ int   g_odd = 0;   // label dtype flag; data-monotone, replay-stable

// ---------------- K0: vectorized convert + zero + dtype detect ----------------
__global__ void k_init(const float4* __restrict__ E4, const int* __restrict__ lab32) {
    int idx = blockIdx.x * blockDim.x + threadIdx.x;   // 65536 threads, 4 f4 each
    #pragma unroll
    for (int h = 0; h < 4; h++) {
        int i = idx + h * 65536;
        float4 v = E4[i];
        __nv_bfloat162* d = (__nv_bfloat162*)(g_Ebf + 4 * (size_t)i);
        d[0] = __floats2bfloat162_rn(v.x, v.y);
        d[1] = __floats2bfloat162_rn(v.z, v.w);
    }
    ((float4*)g_S)[idx] = make_float4(0.f, 0.f, 0.f, 0.f);  // 65536 == NCLS*DK/4
    if (idx < NCLS) g_cnt[idx] = 0;
    if (idx < BN) {
        g_Z[idx] = 0.0f;
        if ((idx & 1) && lab32[idx] != 0) atomicOr(&g_odd, 1);
    }
    if (idx == 0) { g_num = 0.0f; g_den = 0; g_done = 0; }
}

// ---------------- asm helpers ----------------
__device__ __forceinline__ uint32_t smem_u32(const void* p) {
    return (uint32_t)__cvta_generic_to_shared(p);
}
__device__ __forceinline__ void ldsm_x4(uint32_t* r, const void* p) {
    uint32_t a = smem_u32(p);
    asm volatile("ldmatrix.sync.aligned.m8n8.x4.shared.b16 {%0,%1,%2,%3}, [%4];\n"
                 : "=r"(r[0]), "=r"(r[1]), "=r"(r[2]), "=r"(r[3]) : "r"(a));
}
__device__ __forceinline__ void mma16816(float* c, const uint32_t* a, const uint32_t* b) {
    asm volatile(
        "mma.sync.aligned.m16n8k16.row.col.f32.bf16.bf16.f32 "
        "{%0,%1,%2,%3}, {%4,%5,%6,%7}, {%8,%9}, {%0,%1,%2,%3};\n"
        : "+f"(c[0]), "+f"(c[1]), "+f"(c[2]), "+f"(c[3])
        : "r"(a[0]), "r"(a[1]), "r"(a[2]), "r"(a[3]), "r"(b[0]), "r"(b[1]));
}
__device__ __forceinline__ void cpa16(uint32_t s, const void* g) {
    asm volatile("{.reg .u64 p; cvta.to.global.u64 p, %1;"
                 " cp.async.cg.shared.global [%0], [p], 16;}"
                 :: "r"(s), "l"(g) : "memory");
}
#define CPA_COMMIT() asm volatile("cp.async.commit_group;" ::: "memory")
#define CPA_WAIT0()  asm volatile("cp.async.wait_group 0;" ::: "memory")
#define CPA_WAIT1()  asm volatile("cp.async.wait_group 1;" ::: "memory")

__device__ __forceinline__ float ex2f(float x) {
    float r; asm("ex2.approx.f32 %0, %1;" : "=f"(r) : "f"(x)); return r;
}
__device__ __forceinline__ uint32_t pack_h2(float hi, float lo) {
    uint32_t r; asm("cvt.rn.f16x2.f32 %0, %1, %2;" : "=r"(r) : "f"(hi), "f"(lo));
    return r;
}
__device__ __forceinline__ uint32_t ex2h2(uint32_t x) {
    uint32_t r; asm("ex2.approx.f16x2 %0, %1;" : "=r"(r) : "r"(x)); return r;
}
__device__ __forceinline__ uint32_t hadd2(uint32_t a, uint32_t b) {
    uint32_t r; asm("add.f16x2 %0, %1, %2;" : "=r"(r) : "r"(a), "r"(b)); return r;
}
__device__ __forceinline__ void unpk(uint32_t h2, float& lo, float& hi) {
    asm("{.reg .f16 l, h; mov.b32 {l, h}, %2;"
        " cvt.f32.f16 %0, l; cvt.f32.f16 %1, h;}"
        : "=f"(lo), "=f"(hi) : "r"(h2));
}

// tile enumeration: bi<32 -> 33 distances (0..32), bi>=32 -> 32 (0..31)
__device__ __forceinline__ void decode(int g, int& bi, int& d) {
    if (g < 1056) { bi = g / 33; d = g - bi * 33; }
    else          { int h = g - 1056; bi = 32 + (h >> 5); d = h & 31; }
}

// ---------------- K2: symmetric GEMM + streaming exp -> Z ----------------
#define SKEW 136
#define TILE_BYTES (128 * SKEW * 2)   // 34816
#define SM_A 0
#define SM_B0 TILE_BYTES
#define SM_B1 (2 * TILE_BYTES)
#define K2_SMEM (3 * TILE_BYTES)      // 104448 -> 2 CTAs/SM

__device__ __forceinline__ void tile_async(uint32_t dst, const __nv_bfloat16* src, int tid) {
    #pragma unroll
    for (int t = 0; t < 8; t++) {
        int idx = t * 256 + tid;
        int r = idx >> 4, cc = (idx & 15) << 3;
        cpa16(dst + (uint32_t)(r * (SKEW * 2) + cc * 2), src + r * DK + cc);
    }
}

__device__ __forceinline__ void flush_z(float z[4][2], int rowbase, int wm, int lane) {
    #pragma unroll
    for (int mt = 0; mt < 4; mt++)
        #pragma unroll
        for (int h = 0; h < 2; h++) {
            z[mt][h] += __shfl_xor_sync(0xffffffffu, z[mt][h], 1);
            z[mt][h] += __shfl_xor_sync(0xffffffffu, z[mt][h], 2);
        }
    if ((lane & 3) == 0) {
        #pragma unroll
        for (int mt = 0; mt < 4; mt++) {
            int r = rowbase + wm * 64 + mt * 16 + (lane >> 2);
            atomicAdd(&g_Z[r],     z[mt][0] * SCALE);
            atomicAdd(&g_Z[r + 8], z[mt][1] * SCALE);
        }
    }
    #pragma unroll
    for (int mt = 0; mt < 4; mt++) { z[mt][0] = 0.f; z[mt][1] = 0.f; }
}

// epilogue for one computed tile (per-warp). acc consumed, z/col-atomics produced.
__device__ __forceinline__ void epilogue(float acc[4][4][4], int bi, int dv, int jbase,
                                         float z[4][2], int wm, int wn, int lane) {
    if (dv == 0) {
        const int rb = bi * 128 + wm * 64 + (lane >> 2);
        const int cb = jbase + wn * 32 + ((lane & 3) << 1);
        #pragma unroll
        for (int mt = 0; mt < 4; mt++)
            #pragma unroll
            for (int nt = 0; nt < 4; nt++)
                #pragma unroll
                for (int p = 0; p < 4; p++) {
                    int row = rb + mt * 16 + ((p >> 1) << 3);
                    int col = cb + nt * 8 + (p & 1);
                    float e = ex2f(fmaf(acc[mt][nt][p], C1, C0S));
                    if (row == col) e = 0.0f;
                    z[mt][p >> 1] += e;
                }
    } else {
        uint32_t zh[4][2], cah[4];
        #pragma unroll
        for (int mt = 0; mt < 4; mt++) { zh[mt][0] = 0; zh[mt][1] = 0; }
        #pragma unroll
        for (int nt = 0; nt < 4; nt++) cah[nt] = 0;
        #pragma unroll
        for (int mt = 0; mt < 4; mt++)
            #pragma unroll
            for (int nt = 0; nt < 4; nt++) {
                float a0 = fmaf(acc[mt][nt][0], C1, C0S);
                float a1 = fmaf(acc[mt][nt][1], C1, C0S);
                float a2 = fmaf(acc[mt][nt][2], C1, C0S);
                float a3 = fmaf(acc[mt][nt][3], C1, C0S);
                uint32_t h2a = ex2h2(pack_h2(a1, a0));
                uint32_t h2b = ex2h2(pack_h2(a3, a2));
                zh[mt][0] = hadd2(zh[mt][0], h2a);
                zh[mt][1] = hadd2(zh[mt][1], h2b);
                cah[nt]   = hadd2(cah[nt], hadd2(h2a, h2b));
            }
        #pragma unroll
        for (int mt = 0; mt < 4; mt++)
            #pragma unroll
            for (int h = 0; h < 2; h++) {
                float lo, hi; unpk(zh[mt][h], lo, hi);
                z[mt][h] += lo + hi;
            }
        #pragma unroll
        for (int nt = 0; nt < 4; nt++) {
            uint32_t v = cah[nt];
            v = hadd2(v, __shfl_xor_sync(0xffffffffu, v, 4));
            v = hadd2(v, __shfl_xor_sync(0xffffffffu, v, 8));
            v = hadd2(v, __shfl_xor_sync(0xffffffffu, v, 16));
            cah[nt] = v;
        }
        if (lane < 4) {
            const int cb = jbase + wn * 32 + lane * 2;
            #pragma unroll
            for (int nt = 0; nt < 4; nt++) {
                float lo, hi; unpk(cah[nt], lo, hi);
                atomicAdd(&g_Z[cb + nt * 8],     lo * SCALE);
                atomicAdd(&g_Z[cb + nt * 8 + 1], hi * SCALE);
            }
        }
    }
}

__global__ void __launch_bounds__(256, 2) k_main(const float* __restrict__ E,
                                                 const void* __restrict__ labp) {
    extern __shared__ __align__(16) char sm[];
    const uint32_t smb = smem_u32(sm);
    const int tid = threadIdx.x, warp = tid >> 5, lane = tid & 31;
    const int wm = warp >> 2;                // warpgroup: 0 -> rows 0-63, 1 -> rows 64-127
    const int wn = warp & 3;                 // cols wn*32..+32
    const int c  = blockIdx.x;               // 0..295
    const int g0 = (NTILE * c) / NCTA;
    const int g1 = (NTILE * (c + 1)) / NCTA; // 7 or 8 tiles
    const int odd = g_odd;

    int cur_bi, d0; decode(g0, cur_bi, d0);

    tile_async(smb + SM_A,  g_Ebf + (size_t)(cur_bi * 128) * DK, tid);
    tile_async(smb + SM_B0, g_Ebf + (size_t)(((cur_bi + d0) & 63) * 128) * DK, tid);
    CPA_COMMIT();

    float z[4][2];
    #pragma unroll
    for (int mt = 0; mt < 4; mt++) { z[mt][0] = 0.f; z[mt][1] = 0.f; }

    float acc[4][4][4];
    int pdv = 0, pjb = 0;       // previous tile params (for WG1's deferred epilogue)
    bool have_prev = false;

    for (int g = g0; g < g1; g++) {
        const int it  = g - g0;
        const int buf = it & 1;
        int bi, dv; decode(g, bi, dv);
        const int jbase = ((bi + dv) & 63) * 128;

        CPA_WAIT0();
        __syncthreads();   // B(g) visible; buffer being overwritten next is free

        const bool abound = (bi != cur_bi);
        if (abound) {
            tile_async(smb + SM_A, g_Ebf + (size_t)(bi * 128) * DK, tid);
            CPA_COMMIT();
        }
        if (g + 1 < g1) {
            int nbi, ndv; decode(g + 1, nbi, ndv);
            tile_async(smb + (buf ? SM_B0 : SM_B1),
                       g_Ebf + (size_t)(((nbi + ndv) & 63) * 128) * DK, tid);
            CPA_COMMIT();
        }

        // spread class-sum prep early: LDG latency spans the whole step
        if (it < 7) {
            #pragma unroll
            for (int u2 = 0; u2 < 2; u2++) {
                int idx = c * 3584 + (it * 2 + u2) * 256 + tid;
                if (idx < BN * DK) {
                    int row = idx >> 7, d = idx & 127;
                    int v = odd ? ((const int*)labp)[row]
                                : (int)(((const long long*)labp)[row]);
                    if (d == 0) { g_lab[row] = v; atomicAdd(&g_cnt[v], 1); }
                    atomicAdd(&g_S[v * DK + d], E[idx]);
                }
            }
        }

        // WG1: deferred epilogue of tile g-1 (anti-phased vs WG0's MMA)
        if (wm == 1 && have_prev)
            epilogue(acc, cur_bi, pdv, pjb, z, wm, wn, lane);

        if (abound) {
            flush_z(z, cur_bi * 128, wm, lane);   // WG1 flushed after its epi above
            cur_bi = bi;
            if (g + 1 < g1) CPA_WAIT1(); else CPA_WAIT0();
            __syncthreads();                       // A(bi) visible
        }

        const char* As = sm + SM_A;
        const char* Bs = sm + (buf ? SM_B1 : SM_B0);

        #pragma unroll
        for (int mt = 0; mt < 4; mt++)
            #pragma unroll
            for (int nt = 0; nt < 4; nt++)
                #pragma unroll
                for (int p = 0; p < 4; p++) acc[mt][nt][p] = 0.f;

        #pragma unroll
        for (int kc = 0; kc < 8; kc++) {
            uint32_t a[4][4];
            #pragma unroll
            for (int mt = 0; mt < 4; mt++) {
                int r = wm * 64 + mt * 16 + (lane & 15);
                ldsm_x4(a[mt], As + r * (SKEW * 2) + (kc * 16 + ((lane >> 4) << 3)) * 2);
            }
            uint32_t b[4][2];
            #pragma unroll
            for (int np = 0; np < 2; np++) {
                int jr   = wn * 32 + np * 16 + ((lane >> 4) << 3) + (lane & 7);
                int col8 = kc * 16 + (((lane >> 3) & 1) << 3);
                uint32_t r4[4];
                ldsm_x4(r4, Bs + jr * (SKEW * 2) + col8 * 2);
                b[2*np][0]   = r4[0]; b[2*np][1]   = r4[1];
                b[2*np+1][0] = r4[2]; b[2*np+1][1] = r4[3];
            }
            #pragma unroll
            for (int mt = 0; mt < 4; mt++)
                #pragma unroll
                for (int nt = 0; nt < 4; nt++)
                    mma16816(acc[mt][nt], a[mt], b[nt]);
        }

        // WG0: immediate epilogue (anti-phased vs WG1's MMA)
        if (wm == 0)
            epilogue(acc, bi, dv, jbase, z, wm, wn, lane);

        pdv = dv; pjb = jbase; have_prev = true;
    }

    // tail: WG1 still owes the last tile's epilogue
    if (wm == 1 && have_prev)
        epilogue(acc, cur_bi, pdv, pjb, z, wm, wn, lane);
    flush_z(z, cur_bi * 128, wm, lane);
}

// ---------------- K3: per-row finalize + fused scalar write ----------------
__global__ void k_final(const float* __restrict__ E, float* __restrict__ out) {
    int row  = blockIdx.x * 8 + (threadIdx.x >> 5);
    int lane = threadIdx.x & 31;
    __shared__ bool amLast;
    if (row < BN) {
        int c = g_lab[row];
        int pcnt = g_cnt[c] - 1;
        const float* e = E + row * DK;
        const float* s = g_S + c * DK;
        float dS = 0.f, dE = 0.f;
        #pragma unroll
        for (int t = 0; t < 4; t++) {
            float ev = e[lane + 32 * t];
            dS += ev * s[lane + 32 * t];
            dE += ev * ev;
        }
        #pragma unroll
        for (int sh = 16; sh; sh >>= 1) {
            dS += __shfl_xor_sync(0xffffffffu, dS, sh);
            dE += __shfl_xor_sync(0xffffffffu, dE, sh);
        }
        if (lane == 0 && pcnt > 0) {
            float lse = INV_T + logf(g_Z[row]);
            float rm  = (dS - dE) * INV_T / (float)pcnt - lse;
            atomicAdd(&g_num, rm);
            atomicAdd(&g_den, 1);
        }
    }
    __threadfence();
    __syncthreads();
    if (threadIdx.x == 0) {
        unsigned tkt = atomicAdd(&g_done, 1u);
        amLast = (tkt == gridDim.x - 1);
    }
    __syncthreads();
    if (amLast && threadIdx.x == 0) {
        float num = *(volatile float*)&g_num;
        int   den = *(volatile int*)&g_den;
        out[0] = -num / (float)(den > 0 ? den : 1);
    }
}

// ---------------- launch ----------------
extern "C" void kernel_launch(void* const* d_in, const int* in_sizes, int n_in,
                              void* d_out, int out_size) {
    const float* E   = (const float*)d_in[0];
    const void*  lab = d_in[1];
    float*       out = (float*)d_out;
    (void)in_sizes; (void)n_in; (void)out_size;

    cudaFuncSetAttribute(k_main, cudaFuncAttributeMaxDynamicSharedMemorySize, K2_SMEM);

    k_init <<<256, 256>>>((const float4*)E, (const int*)lab);
    k_main <<<NCTA, 256, K2_SMEM>>>(E, lab);
    k_final<<<(BN + 7) / 8, 256>>>(E, out);
}